// round 16
// baseline (speedup 1.0000x reference)
#include <cuda_runtime.h>
#include <cuda_bf16.h>
#include <cuda_fp16.h>
#include <cstdint>
#include <stdint.h>
#include <float.h>
#include <math.h>

// Problem constants
#define B_    4
#define T_    1024
#define FEAT_ 512
#define H_    8
#define DK_   64
#define SPAN_ 100
#define PADL_ 50
#define NTOK_ (B_*T_)
#define NEL_  (NTOK_*FEAT_)

// HMMA GEMM tiling: 128x64 tile, BK=32, double-buffered, fp16 x fp16.
#define GBM_  128
#define GBN_  64
#define BKg   32
#define PADK  40
#define SAF_BYTES (GBM_*PADK*2)
#define SW_BYTES  (GBN_*PADK*2)
#define BUF_BYTES (SAF_BYTES + SW_BYTES)
#define GEMM_SMEM (2*BUF_BYTES)

// MMA attention tiling — fp16 operands, dedicated V buffer, cp.async staging
#define ABT_   128
#define AROWS_ 240
#define ASTR_  72
#define SQ_OFF   0
#define SK_OFF   (SQ_OFF + ABT_*ASTR_*2)       // 18432
#define SV_OFF   (SK_OFF + AROWS_*ASTR_*2)     // 52992
#define SMK_OFF  (SV_OFF + AROWS_*ASTR_*2)     // 87552
#define ATT_SMEM (SMK_OFF + AROWS_*4)          // 88512 -> 2 CTAs/SM

// ---------------------------------------------------------------------------
// Device scratch
// ---------------------------------------------------------------------------
__device__ __half g_pq[NEL_];               // projected q/k/v, fp16
__device__ __half g_pk[NEL_];
__device__ __half g_pv[NEL_];
__device__ __half g_xf[NEL_];               // context, fp16
__device__ __half g_wt[4 * FEAT_ * FEAT_];  // transposed weights, fp16

// ---------------------------------------------------------------------------
// PTX helpers
// ---------------------------------------------------------------------------
__device__ __forceinline__ unsigned smem_u32(const void* p) {
    unsigned a;
    asm("{ .reg .u64 t; cvta.to.shared.u64 t, %1; cvt.u32.u64 %0, t; }" : "=r"(a) : "l"(p));
    return a;
}
__device__ __forceinline__ void mma_fp16(float* c, const unsigned* a, const unsigned* b) {
    asm volatile(
        "mma.sync.aligned.m16n8k16.row.col.f32.f16.f16.f32 "
        "{%0,%1,%2,%3}, {%4,%5,%6,%7}, {%8,%9}, {%0,%1,%2,%3};"
        : "+f"(c[0]), "+f"(c[1]), "+f"(c[2]), "+f"(c[3])
        : "r"(a[0]), "r"(a[1]), "r"(a[2]), "r"(a[3]), "r"(b[0]), "r"(b[1]));
}
__device__ __forceinline__ void ldsm4(unsigned* r, unsigned addr) {
    asm volatile("ldmatrix.sync.aligned.m8n8.x4.shared.b16 {%0,%1,%2,%3}, [%4];"
        : "=r"(r[0]), "=r"(r[1]), "=r"(r[2]), "=r"(r[3]) : "r"(addr));
}
__device__ __forceinline__ void ldsm4t(unsigned* r, unsigned addr) {
    asm volatile("ldmatrix.sync.aligned.m8n8.x4.trans.shared.b16 {%0,%1,%2,%3}, [%4];"
        : "=r"(r[0]), "=r"(r[1]), "=r"(r[2]), "=r"(r[3]) : "r"(addr));
}
__device__ __forceinline__ void cp16(unsigned dst, const void* src) {
    asm volatile("cp.async.cg.shared.global [%0], [%1], 16;" :: "r"(dst), "l"(src));
}
// zfill variant: srcsize 16 (copy) or 0 (zero-fill, src not dereferenced)
__device__ __forceinline__ void cp16z(unsigned dst, const void* src, unsigned srcsize) {
    asm volatile("cp.async.cg.shared.global [%0], [%1], 16, %2;"
        :: "r"(dst), "l"(src), "r"(srcsize));
}
__device__ __forceinline__ void cp_commit() {
    asm volatile("cp.async.commit_group;" ::: "memory");
}
__device__ __forceinline__ void cp_wait1() {
    asm volatile("cp.async.wait_group 1;" ::: "memory");
}
__device__ __forceinline__ void cp_wait0() {
    asm volatile("cp.async.wait_group 0;" ::: "memory");
}
__device__ __forceinline__ unsigned pack_h2(float a, float b) {
    __half2 p = __floats2half2_rn(a, b);
    return *(unsigned*)&p;
}
__device__ __forceinline__ uint4 cvt8(float4 a, float4 b) {
    uint4 r;
    r.x = pack_h2(a.x, a.y);
    r.y = pack_h2(a.z, a.w);
    r.z = pack_h2(b.x, b.y);
    r.w = pack_h2(b.z, b.w);
    return r;
}

// ---------------------------------------------------------------------------
// Transpose + convert weights: W[k][n] fp32 -> Wt[n][k] fp16.
// ---------------------------------------------------------------------------
__global__ __launch_bounds__(256)
void convert_weights_kernel(const float* __restrict__ Wq, const float* __restrict__ Wk,
                            const float* __restrict__ Wv, const float* __restrict__ Wo)
{
    const int z = blockIdx.z;
    const float* W = (z == 0) ? Wq : (z == 1) ? Wk : (z == 2) ? Wv : Wo;
    __half* Tw = g_wt + (size_t)z * FEAT_ * FEAT_;

    __shared__ float tile[32][33];
    const int tx = threadIdx.x, ty = threadIdx.y;
    const int kb = blockIdx.y * 32, nb = blockIdx.x * 32;
#pragma unroll
    for (int i = 0; i < 4; i++)
        tile[ty + i*8][tx] = W[(size_t)(kb + ty + i*8) * FEAT_ + nb + tx];
    __syncthreads();
#pragma unroll
    for (int i = 0; i < 4; i++) {
        const int n = nb + ty + i*8;
        const int kk = kb + tx;
        Tw[(size_t)n * FEAT_ + kk] = __float2half_rn(tile[tx][ty + i*8]);
    }
}

// ---------------------------------------------------------------------------
// fp16 HMMA GEMM core. AFP32: A is fp32 in global, converted during staging
// (LDG->cvt->STS, reg-prefetched 2 chunks ahead). Else A fp16 via cp.async.
// HALF_OUT: write fp16; else fp32 + bias.
// ---------------------------------------------------------------------------
template<bool AFP32, bool HALF_OUT>
__device__ __forceinline__
void gemm_core(const float* __restrict__ Af32, const __half* __restrict__ Af16,
               const __half* __restrict__ Wt,
               const float* __restrict__ bias, float* __restrict__ C,
               __half* __restrict__ Chf,
               int bm, int bn)
{
    extern __shared__ char smg[];
    const unsigned sb = smem_u32(smg);

    const int tid = threadIdx.x;
    const int wid = tid >> 5;
    const int lane = tid & 31;
    const int wm = (wid & 3) * 32;
    const int wn = (wid >> 2) * 32;
    const int q3 = lane >> 3;
    const int l7 = lane & 7;

    const int ar0 = tid >> 2, as0 = tid & 3;
    const int ar1 = (tid + 256) >> 2;
    const int wr0 = tid >> 2, ws0 = tid & 3;

    const size_t arow0 = (size_t)(bm * GBM_ + ar0) * FEAT_ + as0 * 8;
    const size_t arow1 = (size_t)(bm * GBM_ + ar1) * FEAT_ + as0 * 8;
    const unsigned aoff0 = (unsigned)(ar0 * PADK + as0 * 8) * 2;
    const unsigned aoff1 = (unsigned)(ar1 * PADK + as0 * 8) * 2;
    const size_t wrow = (size_t)(bn * GBN_ + wr0) * FEAT_ + ws0 * 8;
    const unsigned woff = (unsigned)(wr0 * PADK + ws0 * 8) * 2;

    float acc[2][4][4] = {};
    float4 rA0a, rA0b, rA1a, rA1b;   // A prefetch regs (AFP32 path)

    const int NIT = FEAT_ / BKg;     // 16

    // ---- prologue: chunk 0 ----
    if (AFP32) {
        const float* p0 = Af32 + arow0;
        const float* p1 = Af32 + arow1;
        float4 x0 = ((const float4*)p0)[0], x1 = ((const float4*)p0)[1];
        float4 y0 = ((const float4*)p1)[0], y1 = ((const float4*)p1)[1];
        *(uint4*)(smg + aoff0) = cvt8(x0, x1);
        *(uint4*)(smg + aoff1) = cvt8(y0, y1);
        // prefetch chunk 1
        const float* q0 = Af32 + arow0 + BKg;
        const float* q1 = Af32 + arow1 + BKg;
        rA0a = ((const float4*)q0)[0];  rA0b = ((const float4*)q0)[1];
        rA1a = ((const float4*)q1)[0];  rA1b = ((const float4*)q1)[1];
    } else {
        cp16(sb + aoff0, Af16 + arow0);
        cp16(sb + aoff1, Af16 + arow1);
    }
    cp16(sb + SAF_BYTES + woff, Wt + wrow);
    cp_commit();

    for (int it = 0; it < NIT; it++) {
        if (it + 1 < NIT) {
            const unsigned base = sb + (unsigned)(((it + 1) & 1) * BUF_BYTES);
            if (!AFP32) {
                cp16(base + aoff0, Af16 + arow0 + (it + 1) * BKg);
                cp16(base + aoff1, Af16 + arow1 + (it + 1) * BKg);
            }
            cp16(base + SAF_BYTES + woff, Wt + wrow + (it + 1) * BKg);
            cp_commit();
            cp_wait1();
        } else {
            cp_wait0();
        }
        __syncthreads();

        const unsigned uB = sb + (unsigned)((it & 1) * BUF_BYTES);
        const unsigned uAf = uB;
        const unsigned uW  = uB + SAF_BYTES;

#pragma unroll
        for (int ks = 0; ks < 2; ks++) {
            const int ko = ks * 16;
            unsigned af[2][4];
            unsigned bw[8];
#pragma unroll
            for (int mf = 0; mf < 2; mf++) {
                const unsigned arow = (unsigned)(wm + mf * 16 + (q3 & 1) * 8 + l7);
                const unsigned ab = (arow * PADK + (unsigned)(ko + (q3 >> 1) * 8)) * 2;
                ldsm4(af[mf], uAf + ab);
            }
            {
                const unsigned nrow = (unsigned)(wn + (q3 >> 1) * 8 + l7);
                const unsigned bb = (nrow * PADK + (unsigned)(ko + (q3 & 1) * 8)) * 2;
                ldsm4(bw, uW + bb);
                const unsigned bb2 = ((nrow + 16) * PADK + (unsigned)(ko + (q3 & 1) * 8)) * 2;
                ldsm4(bw + 4, uW + bb2);
            }
#pragma unroll
            for (int mf = 0; mf < 2; mf++)
#pragma unroll
                for (int nf = 0; nf < 4; nf++)
                    mma_fp16(acc[mf][nf], af[mf], bw + 2 * nf);
        }

        if (AFP32 && it + 1 < NIT) {
            // STS prefetched A chunk into the other buffer (its last readers
            // finished before this iteration's opening barrier)
            char* base = smg + ((it + 1) & 1) * BUF_BYTES;
            *(uint4*)(base + aoff0) = cvt8(rA0a, rA0b);
            *(uint4*)(base + aoff1) = cvt8(rA1a, rA1b);
            if (it + 2 < NIT) {
                const float* q0 = Af32 + arow0 + (it + 2) * BKg;
                const float* q1 = Af32 + arow1 + (it + 2) * BKg;
                rA0a = ((const float4*)q0)[0];  rA0b = ((const float4*)q0)[1];
                rA1a = ((const float4*)q1)[0];  rA1b = ((const float4*)q1)[1];
            }
        }
        __syncthreads();
    }

#pragma unroll
    for (int mf = 0; mf < 2; mf++) {
        const int r0 = bm * GBM_ + wm + mf * 16 + (lane >> 2);
#pragma unroll
        for (int nf = 0; nf < 4; nf++) {
            const int col = bn * GBN_ + wn + nf * 8 + 2 * (lane & 3);
            const float b0 = bias[col], b1 = bias[col + 1];
            const float v00 = acc[mf][nf][0] + b0, v01 = acc[mf][nf][1] + b1;
            const float v10 = acc[mf][nf][2] + b0, v11 = acc[mf][nf][3] + b1;
            if (HALF_OUT) {
                *(unsigned*)(Chf + (size_t)r0 * FEAT_ + col)       = pack_h2(v00, v01);
                *(unsigned*)(Chf + (size_t)(r0 + 8) * FEAT_ + col) = pack_h2(v10, v11);
            } else {
                *(float2*)(C + (size_t)r0 * FEAT_ + col) = make_float2(v00, v01);
                *(float2*)(C + (size_t)(r0 + 8) * FEAT_ + col) = make_float2(v10, v11);
            }
        }
    }
}

// Q/K/V projections: read fp32 inputs directly (fused conversion).
__global__ __launch_bounds__(256, 2)
void hmma_gemm_qkv(const float* __restrict__ q, const float* __restrict__ k,
                   const float* __restrict__ v,
                   const float* __restrict__ bq, const float* __restrict__ bk,
                   const float* __restrict__ bv)
{
    const float* Af;
    const float* bi;
    __half* Ch;
    int wz;
    if (blockIdx.z == 0)      { Af = q; bi = bq; Ch = g_pq; wz = 0; }
    else if (blockIdx.z == 1) { Af = k; bi = bk; Ch = g_pk; wz = 1; }
    else                      { Af = v; bi = bv; Ch = g_pv; wz = 2; }
    gemm_core<true, true>(Af, nullptr, g_wt + (size_t)wz * FEAT_ * FEAT_,
                          bi, nullptr, Ch, blockIdx.x, blockIdx.y);
}

__global__ __launch_bounds__(256, 2)
void hmma_gemm_out(const float* __restrict__ bo, float* __restrict__ out)
{
    gemm_core<false, false>(nullptr, g_xf, g_wt + (size_t)3 * FEAT_ * FEAT_,
                            bo, out, nullptr, blockIdx.x, blockIdx.y);
}

// ---------------------------------------------------------------------------
// MMA band attention — fp16 operands, cp.async staging, dedicated V buffer.
// Q+K = cp.async group A (waited before scores); V = group B (waited before PV).
// ---------------------------------------------------------------------------
__global__ __launch_bounds__(256, 2)
void attn_mma_kernel(const int* __restrict__ mask, const float* __restrict__ span)
{
    extern __shared__ char sm[];
    const unsigned uQ = smem_u32(sm + SQ_OFF);
    const unsigned uK = smem_u32(sm + SK_OFF);
    const unsigned uV = smem_u32(sm + SV_OFF);
    int* smk = (int*)(sm + SMK_OFF);

    const int bx = blockIdx.x, bhz = blockIdx.y;
    const int b = bhz >> 3, h = bhz & 7;
    const int t0 = bx * ABT_;
    const int j0 = t0 - PADL_;
    const int tid = threadIdx.x;
    const int w = tid >> 5, lane = tid & 31;

    // Stage Q (always in-bounds) + K (zfill OOB) — group A
    for (int u = tid; u < ABT_ * 8; u += 256) {
        const int rr = u >> 3, g = u & 7;
        cp16(uQ + (unsigned)(rr * ASTR_ + g * 8) * 2,
             g_pq + (size_t)(b * T_ + t0 + rr) * FEAT_ + h * DK_ + g * 8);
    }
    for (int u = tid; u < AROWS_ * 8; u += 256) {
        const int rr = u >> 3, g = u & 7;
        const int j = j0 + rr;
        const int ok = (j >= 0 && j < T_);
        const int jc = ok ? j : 0;
        cp16z(uK + (unsigned)(rr * ASTR_ + g * 8) * 2,
              g_pk + (size_t)(b * T_ + jc) * FEAT_ + h * DK_ + g * 8,
              ok ? 16u : 0u);
    }
    cp_commit();
    // Stage V — group B (lands under scores+softmax)
    for (int u = tid; u < AROWS_ * 8; u += 256) {
        const int rr = u >> 3, g = u & 7;
        const int j = j0 + rr;
        const int ok = (j >= 0 && j < T_);
        const int jc = ok ? j : 0;
        cp16z(uV + (unsigned)(rr * ASTR_ + g * 8) * 2,
              g_pv + (size_t)(b * T_ + jc) * FEAT_ + h * DK_ + g * 8,
              ok ? 16u : 0u);
    }
    cp_commit();
    // Mask (plain; tiny)
    for (int rr = tid; rr < AROWS_; rr += 256) {
        const int j = j0 + rr;
        smk[rr] = (j >= 0 && j < T_) ? mask[b * T_ + j] : 0;
    }
    cp_wait1();          // Q+K arrived (V may still be in flight)
    __syncthreads();

    const int q3 = lane >> 3;
    const int l7 = lane & 7;

    // Q fragments
    unsigned qf[4][4];
    {
        const unsigned rbase = (unsigned)(w * 16 + (q3 & 1) * 8 + l7);
#pragma unroll
        for (int kk = 0; kk < 4; kk++) {
            const unsigned off = (rbase * ASTR_ + (unsigned)(kk * 16 + (q3 >> 1) * 8)) * 2;
            ldsm4(qf[kk], uQ + off);
        }
    }

    // Scores
    float sacc[16][4] = {};
#pragma unroll
    for (int nt = 0; nt < 8; nt++) {
        const unsigned nrow = (unsigned)(w * 16 + nt * 16 + (q3 >> 1) * 8 + l7);
#pragma unroll
        for (int kk = 0; kk < 4; kk++) {
            const unsigned off = (nrow * ASTR_ + (unsigned)(kk * 16 + (q3 & 1) * 8)) * 2;
            unsigned kb[4];
            ldsm4(kb, uK + off);
            mma_fp16(sacc[2*nt],   qf[kk], &kb[0]);
            mma_fp16(sacc[2*nt+1], qf[kk], &kb[2]);
        }
    }

    // Softmax + adaptive span (V still landing)
    const int r = lane >> 2;
    const int c2 = 2 * (lane & 3);
    const float spanv = span[h];
    float mx0 = -1e30f, mx1 = -1e30f;
#pragma unroll
    for (int nt8 = 0; nt8 < 16; nt8++) {
#pragma unroll
        for (int e = 0; e < 2; e++) {
            const int c = 8 * nt8 + c2 + e;
            const int mv = smk[w * 16 + c];
            const int s0 = c - r;
            const int s1 = c - r - 8;
            const bool v0 = (s0 >= 0) && (s0 < SPAN_) && (mv != 0);
            const bool v1 = (s1 >= 0) && (s1 < SPAN_) && (mv != 0);
            const float x0 = v0 ? sacc[nt8][e]     * 0.125f : -1e30f;
            const float x1 = v1 ? sacc[nt8][2 + e] * 0.125f : -1e30f;
            sacc[nt8][e] = x0;
            sacc[nt8][2 + e] = x1;
            mx0 = fmaxf(mx0, x0);
            mx1 = fmaxf(mx1, x1);
        }
    }
    mx0 = fmaxf(mx0, __shfl_xor_sync(0xffffffffu, mx0, 1));
    mx0 = fmaxf(mx0, __shfl_xor_sync(0xffffffffu, mx0, 2));
    mx1 = fmaxf(mx1, __shfl_xor_sync(0xffffffffu, mx1, 1));
    mx1 = fmaxf(mx1, __shfl_xor_sync(0xffffffffu, mx1, 2));

    float E0 = 0.f, S0 = 0.f, E1 = 0.f, S1 = 0.f;
#pragma unroll
    for (int nt8 = 0; nt8 < 16; nt8++) {
#pragma unroll
        for (int e = 0; e < 2; e++) {
            const int c = 8 * nt8 + c2 + e;
            const int s0 = c - r;
            const int s1 = c - r - 8;
            const float sf0 = fminf(fmaxf(((float)s0 - 99.0f + spanv * 100.0f) * 0.5f + 1.0f, 0.f), 1.f);
            const float sf1 = fminf(fmaxf(((float)s1 - 99.0f + spanv * 100.0f) * 0.5f + 1.0f, 0.f), 1.f);
            const float e0 = __expf(sacc[nt8][e] - mx0);
            const float e1 = __expf(sacc[nt8][2 + e] - mx1);
            E0 += e0; S0 += e0 * sf0;
            E1 += e1; S1 += e1 * sf1;
            sacc[nt8][e] = e0 * sf0;
            sacc[nt8][2 + e] = e1 * sf1;
        }
    }
    E0 += __shfl_xor_sync(0xffffffffu, E0, 1);  E0 += __shfl_xor_sync(0xffffffffu, E0, 2);
    S0 += __shfl_xor_sync(0xffffffffu, S0, 1);  S0 += __shfl_xor_sync(0xffffffffu, S0, 2);
    E1 += __shfl_xor_sync(0xffffffffu, E1, 1);  E1 += __shfl_xor_sync(0xffffffffu, E1, 2);
    S1 += __shfl_xor_sync(0xffffffffu, S1, 1);  S1 += __shfl_xor_sync(0xffffffffu, S1, 2);
    const float inv0 = (mx0 > -1e29f) ? 1.0f / (S0 + 1e-8f * E0) : 0.f;
    const float inv1 = (mx1 > -1e29f) ? 1.0f / (S1 + 1e-8f * E1) : 0.f;

    // Repack P -> fp16 A-fragments
    unsigned pa[8][4];
#pragma unroll
    for (int j8 = 0; j8 < 8; j8++) {
        pa[j8][0] = pack_h2(sacc[2*j8][0]*inv0,   sacc[2*j8][1]*inv0);
        pa[j8][1] = pack_h2(sacc[2*j8][2]*inv1,   sacc[2*j8][3]*inv1);
        pa[j8][2] = pack_h2(sacc[2*j8+1][0]*inv0, sacc[2*j8+1][1]*inv0);
        pa[j8][3] = pack_h2(sacc[2*j8+1][2]*inv1, sacc[2*j8+1][3]*inv1);
    }

    cp_wait0();          // V arrived
    __syncthreads();

    // O = P · V
    float oacc[8][4] = {};
#pragma unroll
    for (int kk2 = 0; kk2 < 8; kk2++) {
        const unsigned krow = (unsigned)(w * 16 + kk2 * 16 + (q3 & 1) * 8 + l7);
#pragma unroll
        for (int nt = 0; nt < 4; nt++) {
            const unsigned off = (krow * ASTR_ + (unsigned)(nt * 16 + (q3 >> 1) * 8)) * 2;
            unsigned vb[4];
            ldsm4t(vb, uV + off);
            mma_fp16(oacc[2*nt],   pa[kk2], &vb[0]);
            mma_fp16(oacc[2*nt+1], pa[kk2], &vb[2]);
        }
    }

    // Write context fp16
    const int tr = t0 + w * 16 + r;
#pragma unroll
    for (int nf = 0; nf < 8; nf++) {
        const int col = 8 * nf + c2;
        const size_t i0 = (size_t)(b * T_ + tr) * FEAT_ + h * DK_ + col;
        const size_t i1 = (size_t)(b * T_ + tr + 8) * FEAT_ + h * DK_ + col;
        *(unsigned*)(g_xf + i0) = pack_h2(oacc[nf][0], oacc[nf][1]);
        *(unsigned*)(g_xf + i1) = pack_h2(oacc[nf][2], oacc[nf][3]);
    }
}

// ---------------------------------------------------------------------------
// Launch (4 kernels; input conversion fused into qkv GEMM)
// ---------------------------------------------------------------------------
extern "C" void kernel_launch(void* const* d_in, const int* in_sizes, int n_in,
                              void* d_out, int out_size)
{
    (void)in_sizes; (void)n_in; (void)out_size;
    const float* query = (const float*)d_in[0];
    const float* key   = (const float*)d_in[1];
    const float* value = (const float*)d_in[2];
    const int*   mask  = (const int*)  d_in[3];
    const float* Wq    = (const float*)d_in[4];
    const float* bq    = (const float*)d_in[5];
    const float* Wk    = (const float*)d_in[6];
    const float* bk    = (const float*)d_in[7];
    const float* Wv    = (const float*)d_in[8];
    const float* bv    = (const float*)d_in[9];
    const float* Wo    = (const float*)d_in[10];
    const float* bo    = (const float*)d_in[11];
    const float* span  = (const float*)d_in[12];
    float* out = (float*)d_out;

    static int attr_set = 0;
    if (!attr_set) {
        cudaFuncSetAttribute(attn_mma_kernel, cudaFuncAttributeMaxDynamicSharedMemorySize, ATT_SMEM);
        attr_set = 1;
    }

    convert_weights_kernel<<<dim3(16, 16, 4), dim3(32, 8)>>>(Wq, Wk, Wv, Wo);
    hmma_gemm_qkv<<<dim3(NTOK_/GBM_, FEAT_/GBN_, 3), 256, GEMM_SMEM>>>(query, key, value, bq, bk, bv);
    attn_mma_kernel<<<dim3(T_/ABT_, B_*H_), 256, ATT_SMEM>>>(mask, span);
    hmma_gemm_out<<<dim3(NTOK_/GBM_, FEAT_/GBN_), 256, GEMM_SMEM>>>(bo, out);
}